// round 2
// baseline (speedup 1.0000x reference)
#include <cuda_runtime.h>
#include <math.h>

// ---------------------------------------------------------------------------
// BinaryCQV quantum-circuit end-to-end, warp-per-sample statevector sim.
// 10 qubits -> 1024 amps -> 32 complex amps per lane (bits[0:4]=reg, bits[5:9]=lane).
// ---------------------------------------------------------------------------

#define NQ          10
#define INPUT_DIM   49
#define BATCH       2048
#define WARPS_PB    8
#define THREADS_PB  (WARPS_PB * 32)
#define NBLOCKS     (BATCH / WARPS_PB)
#define PI_F        3.14159265358979323846f

#define FULLMASK 0xffffffffu

// ---- RY on qubit Q: [[c,-s],[s,c]] on (|0>,|1>) pair ----
template<int Q>
__device__ __forceinline__ void rot_y(float (&ar)[32], float (&ai)[32],
                                      float c, float s, int lane) {
    if constexpr (Q < 5) {
        #pragma unroll
        for (int r = 0; r < 32; ++r) {
            if (!(r & (1 << Q))) {
                const int r1 = r | (1 << Q);
                float a0r = ar[r],  a0i = ai[r];
                float a1r = ar[r1], a1i = ai[r1];
                ar[r]  = c * a0r - s * a1r;
                ai[r]  = c * a0i - s * a1i;
                ar[r1] = c * a1r + s * a0r;
                ai[r1] = c * a1i + s * a0i;
            }
        }
    } else {
        const int m = 1 << (Q - 5);
        const float sgn = (lane & m) ? s : -s;
        #pragma unroll
        for (int r = 0; r < 32; ++r) {
            float pr = __shfl_xor_sync(FULLMASK, ar[r], m);
            float pi = __shfl_xor_sync(FULLMASK, ai[r], m);
            ar[r] = c * ar[r] + sgn * pr;
            ai[r] = c * ai[r] + sgn * pi;
        }
    }
}

// ---- RX on qubit Q: [[c,-is],[-is,c]]  (symmetric): new = c*own - i*s*partner ----
template<int Q>
__device__ __forceinline__ void rot_x(float (&ar)[32], float (&ai)[32],
                                      float c, float s, int lane) {
    (void)lane;
    if constexpr (Q < 5) {
        #pragma unroll
        for (int r = 0; r < 32; ++r) {
            if (!(r & (1 << Q))) {
                const int r1 = r | (1 << Q);
                float a0r = ar[r],  a0i = ai[r];
                float a1r = ar[r1], a1i = ai[r1];
                ar[r]  = c * a0r + s * a1i;
                ai[r]  = c * a0i - s * a1r;
                ar[r1] = c * a1r + s * a0i;
                ai[r1] = c * a1i - s * a0r;
            }
        }
    } else {
        const int m = 1 << (Q - 5);
        #pragma unroll
        for (int r = 0; r < 32; ++r) {
            float pr = __shfl_xor_sync(FULLMASK, ar[r], m);
            float pi = __shfl_xor_sync(FULLMASK, ai[r], m);
            ar[r] = c * ar[r] + s * pi;
            ai[r] = c * ai[r] - s * pr;
        }
    }
}

// ---- CNOT control C -> target T (C = T-1 in this arch) ----
template<int C, int T>
__device__ __forceinline__ void cnot(float (&ar)[32], float (&ai)[32], int lane) {
    if constexpr (T < 5) {
        // both bits register-local: pure register permutation
        #pragma unroll
        for (int r = 0; r < 32; ++r) {
            if ((r & (1 << C)) && !(r & (1 << T))) {
                const int r1 = r | (1 << T);
                float tr = ar[r], ti = ai[r];
                ar[r] = ar[r1]; ai[r] = ai[r1];
                ar[r1] = tr;    ai[r1] = ti;
            }
        }
    } else if constexpr (C < 5) {
        // control local (bit 4), target = lane bit 0: swap across lanes where r bit C set
        #pragma unroll
        for (int r = 0; r < 32; ++r) {
            float pr = __shfl_xor_sync(FULLMASK, ar[r], 1 << (T - 5));
            float pi = __shfl_xor_sync(FULLMASK, ai[r], 1 << (T - 5));
            if (r & (1 << C)) { ar[r] = pr; ai[r] = pi; }
        }
    } else {
        // both lane bits: predicated exchange
        const int mt = 1 << (T - 5);
        const bool cc = (lane >> (C - 5)) & 1;
        #pragma unroll
        for (int r = 0; r < 32; ++r) {
            float pr = __shfl_xor_sync(FULLMASK, ar[r], mt);
            float pi = __shfl_xor_sync(FULLMASK, ai[r], mt);
            ar[r] = cc ? pr : ar[r];
            ai[r] = cc ? pi : ai[r];
        }
    }
}

__global__ void __launch_bounds__(THREADS_PB)
cqv_kernel(const float* __restrict__ x,          // (2048, 49)
           const float* __restrict__ theta,      // (30,)
           const float* __restrict__ alpha_raw,  // (49,)
           const float* __restrict__ beta_raw,   // (49,)
           const float* __restrict__ head_w,     // (1, 10)
           const float* __restrict__ head_b,     // (1,)
           const float* __restrict__ logit_scale,// scalar
           float* __restrict__ out)              // (2048, 1)
{
    __shared__ float sA[INPUT_DIM];
    __shared__ float sB[INPUT_DIM];
    __shared__ float sC[WARPS_PB][64];
    __shared__ float sS[WARPS_PB][64];

    const int tid  = threadIdx.x;
    const int warp = tid >> 5;
    const int lane = tid & 31;
    const int sample = blockIdx.x * WARPS_PB + warp;

    // ---- Phase A: encoder params (block-wide, once) ----
    if (tid < INPUT_DIM) {
        float a = alpha_raw[tid];
        sA[tid] = log1pf(expf(a)) + 1e-6f;       // softplus + eps
        sB[tid] = tanhf(beta_raw[tid]);          // * ENC_BETA_MAX (=1)
    }
    __syncthreads();

    // ---- Phase B: distribute the 60 sincos across lanes into per-warp table ----
    // gate index g = b*20 + q (encoding RY) or b*20 + 10 + q (trainable RX)
    for (int g = lane; g < 60; g += 32) {
        const int b = g / 20;
        const int k = g - 20 * b;
        float half;
        if (k < 10) {
            const int q = k;
            const int f = (b * NQ + q) % INPUT_DIM;
            float ang = PI_F * (sA[f] * x[sample * INPUT_DIM + f] + sB[f]);
            half = 0.5f * ang;
        } else {
            half = 0.5f * theta[b * NQ + (k - 10)];
        }
        float s, c;
        sincosf(half, &s, &c);
        sC[warp][g] = c;
        sS[warp][g] = s;
    }
    __syncwarp();

    // ---- Phase C: circuit ----
    float ar[32], ai[32];
    #pragma unroll
    for (int r = 0; r < 32; ++r) { ar[r] = 0.f; ai[r] = 0.f; }
    if (lane == 0) ar[0] = 1.0f;

    #pragma unroll 1
    for (int b = 0; b < 3; ++b) {
        const float* cw = sC[warp];
        const float* sw = sS[warp];
        const int e0 = b * 20;       // encoding RY base
        const int t0 = b * 20 + 10;  // trainable RX base

        #define RYG(Q) rot_y<Q>(ar, ai, cw[e0 + Q], sw[e0 + Q], lane)
        RYG(0); RYG(1); RYG(2); RYG(3); RYG(4);
        RYG(5); RYG(6); RYG(7); RYG(8); RYG(9);
        #undef RYG

        #define RXG(Q) rot_x<Q>(ar, ai, cw[t0 + Q], sw[t0 + Q], lane)
        RXG(0); RXG(1); RXG(2); RXG(3); RXG(4);
        RXG(5); RXG(6); RXG(7); RXG(8); RXG(9);
        #undef RXG

        cnot<0,1>(ar, ai, lane);
        cnot<1,2>(ar, ai, lane);
        cnot<2,3>(ar, ai, lane);
        cnot<3,4>(ar, ai, lane);
        cnot<4,5>(ar, ai, lane);
        cnot<5,6>(ar, ai, lane);
        cnot<6,7>(ar, ai, lane);
        cnot<7,8>(ar, ai, lane);
        cnot<8,9>(ar, ai, lane);
    }

    // ---- Phase D: readout  raw = sum_i p_i * (sum_q w_q * (1-2 bit_q(i))) ----
    float w[NQ];
    #pragma unroll
    for (int q = 0; q < NQ; ++q) w[q] = head_w[q];

    float coefLane = 0.f;
    #pragma unroll
    for (int q = 5; q < NQ; ++q)
        coefLane += ((lane >> (q - 5)) & 1) ? -w[q] : w[q];

    float acc = 0.f;
    #pragma unroll
    for (int r = 0; r < 32; ++r) {
        float p = ar[r] * ar[r] + ai[r] * ai[r];
        float coef = coefLane;
        #pragma unroll
        for (int q = 0; q < 5; ++q)
            coef += ((r >> q) & 1) ? -w[q] : w[q];
        acc += p * coef;
    }
    #pragma unroll
    for (int off = 16; off > 0; off >>= 1)
        acc += __shfl_xor_sync(FULLMASK, acc, off);

    if (lane == 0) {
        float raw = acc + head_b[0];
        float scale = fminf(fmaxf(logit_scale[0], 0.5f), 80.0f);
        float v = scale * raw;
        v = fminf(fmaxf(v, -30.0f), 30.0f);
        out[sample] = v;
    }
}

extern "C" void kernel_launch(void* const* d_in, const int* in_sizes, int n_in,
                              void* d_out, int out_size) {
    (void)in_sizes; (void)n_in; (void)out_size;
    const float* x           = (const float*)d_in[0];
    const float* theta       = (const float*)d_in[1];
    const float* alpha_raw   = (const float*)d_in[2];
    const float* beta_raw    = (const float*)d_in[3];
    const float* head_w      = (const float*)d_in[4];
    const float* head_b      = (const float*)d_in[5];
    const float* logit_scale = (const float*)d_in[6];
    float* out = (float*)d_out;

    cqv_kernel<<<NBLOCKS, THREADS_PB>>>(x, theta, alpha_raw, beta_raw,
                                        head_w, head_b, logit_scale, out);
}

// round 3
// speedup vs baseline: 1.1367x; 1.1367x over previous
#include <cuda_runtime.h>
#include <math.h>

// ---------------------------------------------------------------------------
// BinaryCQV end-to-end, warp-per-sample statevector sim, CNOT-free formulation.
// Physical index i (10 bits): bits0-4 = register r, bits5-9 = lane.
// Invariant: stored[i] = psi[A*i]; CNOT chains update A (I -> L -> L^2 -> L^3)
// with ZERO data movement. Rotations use masks m = A^{-1} e_q and sign
// parity(row_q(A) & i), all compile-time.
// Layer 1 (product state from |0>) is built directly: ~62 complex mults.
// ---------------------------------------------------------------------------

#define FULLMASK 0xffffffffu
#define PI_F 3.14159265358979323846f
#define BATCH 2048
#define INPUT_DIM 49

// ---- generic RY: pair mask M (10-bit), role mask ROLE (10-bit).
// new_i = c*a_i + sign_i * a_{i^M},  sign_i = parity(ROLE & i) ? +s : -s
template<int M, int ROLE>
__device__ __forceinline__ void ry_g(float (&ar)[32], float (&ai)[32],
                                     float c, float s, int lane) {
    constexpr int MR = M & 31;
    constexpr int ML = (M >> 5) & 31;
    constexpr int RR = ROLE & 31;
    constexpr int RL = (ROLE >> 5) & 31;
    float bs;  // sign for parity(r&RR)==0 given this lane
    if constexpr (RL != 0) bs = (__popc(lane & RL) & 1) ? s : -s;
    else                   bs = -s;
    if constexpr (ML == 0) {
        #pragma unroll
        for (int r = 0; r < 32; ++r) {
            const int r1 = r ^ MR;
            if (r < r1) {
                float sg  = (__popc(r & RR) & 1) ? -bs : bs;
                float a0r = ar[r],  a0i = ai[r];
                float a1r = ar[r1], a1i = ai[r1];
                ar[r]  = c * a0r + sg * a1r;
                ai[r]  = c * a0i + sg * a1i;
                ar[r1] = c * a1r - sg * a0r;
                ai[r1] = c * a1i - sg * a0i;
            }
        }
    } else if constexpr (MR == 0) {
        #pragma unroll
        for (int r = 0; r < 32; ++r) {
            float pr = __shfl_xor_sync(FULLMASK, ar[r], ML);
            float pi = __shfl_xor_sync(FULLMASK, ai[r], ML);
            float sg = (__popc(r & RR) & 1) ? -bs : bs;
            ar[r] = c * ar[r] + sg * pr;
            ai[r] = c * ai[r] + sg * pi;
        }
    } else {
        #pragma unroll
        for (int r = 0; r < 32; ++r) {
            const int r1 = r ^ MR;
            if (r < r1) {
                float p0r = __shfl_xor_sync(FULLMASK, ar[r1], ML);
                float p0i = __shfl_xor_sync(FULLMASK, ai[r1], ML);
                float p1r = __shfl_xor_sync(FULLMASK, ar[r],  ML);
                float p1i = __shfl_xor_sync(FULLMASK, ai[r],  ML);
                float sg0 = (__popc(r  & RR) & 1) ? -bs : bs;
                float sg1 = (__popc(r1 & RR) & 1) ? -bs : bs;
                ar[r]  = c * ar[r]  + sg0 * p0r;
                ai[r]  = c * ai[r]  + sg0 * p0i;
                ar[r1] = c * ar[r1] + sg1 * p1r;
                ai[r1] = c * ai[r1] + sg1 * p1i;
            }
        }
    }
}

// ---- generic RX (symmetric, role-free): new_i = c*a_i - i*s*a_{i^M}
template<int M>
__device__ __forceinline__ void rx_g(float (&ar)[32], float (&ai)[32],
                                     float c, float s) {
    constexpr int MR = M & 31;
    constexpr int ML = (M >> 5) & 31;
    if constexpr (ML == 0) {
        #pragma unroll
        for (int r = 0; r < 32; ++r) {
            const int r1 = r ^ MR;
            if (r < r1) {
                float a0r = ar[r],  a0i = ai[r];
                float a1r = ar[r1], a1i = ai[r1];
                ar[r]  = c * a0r + s * a1i;
                ai[r]  = c * a0i - s * a1r;
                ar[r1] = c * a1r + s * a0i;
                ai[r1] = c * a1i - s * a0r;
            }
        }
    } else if constexpr (MR == 0) {
        #pragma unroll
        for (int r = 0; r < 32; ++r) {
            float pr = __shfl_xor_sync(FULLMASK, ar[r], ML);
            float pi = __shfl_xor_sync(FULLMASK, ai[r], ML);
            ar[r] = c * ar[r] + s * pi;
            ai[r] = c * ai[r] - s * pr;
        }
    } else {
        #pragma unroll
        for (int r = 0; r < 32; ++r) {
            const int r1 = r ^ MR;
            if (r < r1) {
                float p0r = __shfl_xor_sync(FULLMASK, ar[r1], ML);
                float p0i = __shfl_xor_sync(FULLMASK, ai[r1], ML);
                float p1r = __shfl_xor_sync(FULLMASK, ar[r],  ML);
                float p1i = __shfl_xor_sync(FULLMASK, ai[r],  ML);
                ar[r]  = c * ar[r]  + s * p0i;
                ai[r]  = c * ai[r]  - s * p0r;
                ar[r1] = c * ar[r1] + s * p1i;
                ai[r1] = c * ai[r1] - s * p1r;
            }
        }
    }
}

__global__ void __launch_bounds__(32)
cqv_kernel(const float* __restrict__ x,          // (2048, 49)
           const float* __restrict__ theta,      // (30,)
           const float* __restrict__ alpha_raw,  // (49,)
           const float* __restrict__ beta_raw,   // (49,)
           const float* __restrict__ head_w,     // (1, 10)
           const float* __restrict__ head_b,     // (1,)
           const float* __restrict__ logit_scale,// scalar
           float* __restrict__ out)              // (2048,)
{
    __shared__ float cg[64];
    __shared__ float sg[64];

    const int lane = threadIdx.x;
    const int sample = blockIdx.x;

    // ---- Phase A: all 60 half-angle sincos, distributed over lanes ----
    // gate g = b*20 + k; k<10: encoding RY (feature f = b*10+k, f<=29<49),
    // k>=10: trainable RX theta[b*10 + k-10].
    #pragma unroll
    for (int t = 0; t < 2; ++t) {
        const int g = lane + 32 * t;
        if (g < 60) {
            const int b = g / 20;
            const int k = g - 20 * b;
            float half;
            if (k < 10) {
                const int f = b * 10 + k;
                const float a = alpha_raw[f];
                // numerically stable softplus + 1e-6
                const float sp = fmaxf(a, 0.f) + log1pf(expf(-fabsf(a))) + 1e-6f;
                const float bt = tanhf(beta_raw[f]);
                half = 0.5f * PI_F * (sp * x[sample * INPUT_DIM + f] + bt);
            } else {
                half = 0.5f * theta[b * 10 + (k - 10)];
            }
            float s_, c_;
            sincosf(half, &s_, &c_);
            cg[g] = c_;
            sg[g] = s_;
        }
    }
    __syncwarp();

    // ---- Phase B: layer-1 product state (A = I) ----
    // f_q(0) = (cx*cy, -sx*sy), f_q(1) = (cx*sy, -sx*cy)
    float ar[32], ai[32];
    {
        // per-lane factor over qubits 5..9 (lane bits)
        float lfr = 1.f, lfi = 0.f;
        #pragma unroll
        for (int q = 5; q < 10; ++q) {
            const float cy = cg[q],      sy = sg[q];
            const float cx = cg[10 + q], sx = sg[10 + q];
            const int bbit = (lane >> (q - 5)) & 1;
            const float fre =  cx * (bbit ? sy : cy);
            const float fim = -sx * (bbit ? cy : sy);
            const float nr = lfr * fre - lfi * fim;
            const float ni = lfr * fim + lfi * fre;
            lfr = nr; lfi = ni;
        }
        ar[0] = lfr; ai[0] = lfi;
        // doubling over register qubits 0..4
        #pragma unroll
        for (int k = 0; k < 5; ++k) {
            const float cy = cg[k],      sy = sg[k];
            const float cx = cg[10 + k], sx = sg[10 + k];
            const float f0r = cx * cy, f0i = -sx * sy;
            const float f1r = cx * sy, f1i = -sx * cy;
            #pragma unroll
            for (int r = 0; r < 16; ++r) {
                if (r < (1 << k)) {
                    const float br_ = ar[r], bi_ = ai[r];
                    ar[r + (1 << k)] = br_ * f1r - bi_ * f1i;
                    ai[r + (1 << k)] = br_ * f1i + bi_ * f1r;
                    ar[r] = br_ * f0r - bi_ * f0i;
                    ai[r] = br_ * f0i + bi_ * f0r;
                }
            }
        }
    }
    // layer-1 CNOT chain: A = L (prefix-sum matrix). Free.

    // ---- Layer 2 gates (A = L): m_q = e_q ^ e_{q+1}, role_q = bits[0..q] ----
    {
        const float* C = cg + 20;
        const float* S = sg + 20;
        ry_g<0x003, 0x001>(ar, ai, C[0], S[0], lane);
        ry_g<0x006, 0x003>(ar, ai, C[1], S[1], lane);
        ry_g<0x00C, 0x007>(ar, ai, C[2], S[2], lane);
        ry_g<0x018, 0x00F>(ar, ai, C[3], S[3], lane);
        ry_g<0x030, 0x01F>(ar, ai, C[4], S[4], lane);
        ry_g<0x060, 0x03F>(ar, ai, C[5], S[5], lane);
        ry_g<0x0C0, 0x07F>(ar, ai, C[6], S[6], lane);
        ry_g<0x180, 0x0FF>(ar, ai, C[7], S[7], lane);
        ry_g<0x300, 0x1FF>(ar, ai, C[8], S[8], lane);
        ry_g<0x200, 0x3FF>(ar, ai, C[9], S[9], lane);
        rx_g<0x003>(ar, ai, C[10], S[10]);
        rx_g<0x006>(ar, ai, C[11], S[11]);
        rx_g<0x00C>(ar, ai, C[12], S[12]);
        rx_g<0x018>(ar, ai, C[13], S[13]);
        rx_g<0x030>(ar, ai, C[14], S[14]);
        rx_g<0x060>(ar, ai, C[15], S[15]);
        rx_g<0x0C0>(ar, ai, C[16], S[16]);
        rx_g<0x180>(ar, ai, C[17], S[17]);
        rx_g<0x300>(ar, ai, C[18], S[18]);
        rx_g<0x200>(ar, ai, C[19], S[19]);
    }
    // layer-2 CNOT chain: A = L^2. Free.

    // ---- Layer 3 gates (A = L^2): m_q = e_q ^ e_{q+2}, role_q = {q,q-2,...} ----
    {
        const float* C = cg + 40;
        const float* S = sg + 40;
        ry_g<0x005, 0x001>(ar, ai, C[0], S[0], lane);
        ry_g<0x00A, 0x002>(ar, ai, C[1], S[1], lane);
        ry_g<0x014, 0x005>(ar, ai, C[2], S[2], lane);
        ry_g<0x028, 0x00A>(ar, ai, C[3], S[3], lane);
        ry_g<0x050, 0x015>(ar, ai, C[4], S[4], lane);
        ry_g<0x0A0, 0x02A>(ar, ai, C[5], S[5], lane);
        ry_g<0x140, 0x055>(ar, ai, C[6], S[6], lane);
        ry_g<0x280, 0x0AA>(ar, ai, C[7], S[7], lane);
        ry_g<0x100, 0x155>(ar, ai, C[8], S[8], lane);
        ry_g<0x200, 0x2AA>(ar, ai, C[9], S[9], lane);
        rx_g<0x005>(ar, ai, C[10], S[10]);
        rx_g<0x00A>(ar, ai, C[11], S[11]);
        rx_g<0x014>(ar, ai, C[12], S[12]);
        rx_g<0x028>(ar, ai, C[13], S[13]);
        rx_g<0x050>(ar, ai, C[14], S[14]);
        rx_g<0x0A0>(ar, ai, C[15], S[15]);
        rx_g<0x140>(ar, ai, C[16], S[16]);
        rx_g<0x280>(ar, ai, C[17], S[17]);
        rx_g<0x100>(ar, ai, C[18], S[18]);
        rx_g<0x200>(ar, ai, C[19], S[19]);
    }
    // layer-3 CNOT chain: A = L^3 = I + S + S^4 + S^5 + S^8 + S^9. Free.

    // ---- Readout: bit_q(logical) = parity(row_q(L^3) & i) ----
    // row masks (reg part / lane part):
    const int RREG[10] = {0x01, 0x03, 0x06, 0x0C, 0x19, 0x13, 0x06, 0x0C, 0x19, 0x13};
    const int RLAN[10] = {0x00, 0x00, 0x00, 0x00, 0x00, 0x01, 0x03, 0x06, 0x0C, 0x19};

    float wl[10];
    #pragma unroll
    for (int q = 0; q < 10; ++q) {
        const float w = head_w[q];
        wl[q] = (__popc(lane & RLAN[q]) & 1) ? -w : w;
    }

    float acc = 0.f;
    #pragma unroll
    for (int r = 0; r < 32; ++r) {
        const float p = ar[r] * ar[r] + ai[r] * ai[r];
        float coef = 0.f;
        #pragma unroll
        for (int q = 0; q < 10; ++q)
            coef += (__popc(r & RREG[q]) & 1) ? -wl[q] : wl[q];
        acc = fmaf(p, coef, acc);
    }
    #pragma unroll
    for (int off = 16; off > 0; off >>= 1)
        acc += __shfl_xor_sync(FULLMASK, acc, off);

    if (lane == 0) {
        const float raw = acc + head_b[0];
        const float scale = fminf(fmaxf(logit_scale[0], 0.5f), 80.0f);
        float v = scale * raw;
        v = fminf(fmaxf(v, -30.0f), 30.0f);
        out[sample] = v;
    }
}

extern "C" void kernel_launch(void* const* d_in, const int* in_sizes, int n_in,
                              void* d_out, int out_size) {
    (void)in_sizes; (void)n_in; (void)out_size;
    const float* x           = (const float*)d_in[0];
    const float* theta       = (const float*)d_in[1];
    const float* alpha_raw   = (const float*)d_in[2];
    const float* beta_raw    = (const float*)d_in[3];
    const float* head_w      = (const float*)d_in[4];
    const float* head_b      = (const float*)d_in[5];
    const float* logit_scale = (const float*)d_in[6];
    float* out = (float*)d_out;

    cqv_kernel<<<BATCH, 32>>>(x, theta, alpha_raw, beta_raw,
                              head_w, head_b, logit_scale, out);
}

// round 8
// speedup vs baseline: 1.2604x; 1.1089x over previous
#include <cuda_runtime.h>
#include <math.h>

// ---------------------------------------------------------------------------
// BinaryCQV end-to-end, warp-per-sample statevector sim.
// CNOT-free (GF(2) frame tracking) + fused SU(2) gates (RX_q*RY_q per qubit
// per layer via commutation). 10 qubits: bits0-4 = register, bits5-9 = lane.
// Invariant: stored[i] = psi[A*i]; gate on logical q pairs (i, i^m),
// m = A^{-1} e_q, logical bit = parity(row_q(A) & i). All masks compile-time.
// ---------------------------------------------------------------------------

#define FULLMASK 0xffffffffu
#define PI_F 3.14159265358979323846f
#define BATCH 2048
#define INPUT_DIM 49

// Fused SU(2) gate U=[[a,-b*],[b,a*]] with parity-dependent conjugation:
// element i (parity p = parity(ROLE&i), sigma = p?+1:-1):
//   new_r = Ar*xr + sigma*Ai*xi + sigma*Br*pr - Bi*pi
//   new_i = Ar*xi - sigma*Ai*xr + sigma*Br*pi + Bi*pr
// where (pr,pi) = partner amplitude at i^M.
template<int M, int ROLE>
__device__ __forceinline__ void su2_g(float (&xr)[32], float (&xi)[32],
                                      float Ar, float Ai, float Br, float Bi,
                                      int lane) {
    constexpr int MR = M & 31;
    constexpr int ML = (M >> 5) & 31;
    constexpr int RR = ROLE & 31;
    constexpr int RL = (ROLE >> 5) & 31;

    // coefficients for elements with parity(r&RR)==0 (lane parity folded in)
    float Ai0, Br0;
    if constexpr (RL != 0) {
        const bool lp = (__popc(lane & RL) & 1);
        Ai0 = lp ? Ai : -Ai;
        Br0 = lp ? Br : -Br;
    } else {
        Ai0 = -Ai;
        Br0 = -Br;
    }
    const float Ai1 = -Ai0, Br1 = -Br0;

    if constexpr (ML == 0) {
        // register-local pairs
        #pragma unroll
        for (int r = 0; r < 32; ++r) {
            const int r1 = r ^ MR;
            if (r < r1) {
                const bool p0 = (__popc(r & RR) & 1);
                const float aP = p0 ? Ai1 : Ai0, bP = p0 ? Br1 : Br0;
                const float aQ = p0 ? Ai0 : Ai1, bQ = p0 ? Br0 : Br1;
                const float x0r = xr[r],  x0i = xi[r];
                const float x1r = xr[r1], x1i = xi[r1];
                xr[r]  = Ar * x0r + aP * x0i + bP * x1r - Bi * x1i;
                xi[r]  = Ar * x0i - aP * x0r + bP * x1i + Bi * x1r;
                xr[r1] = Ar * x1r + aQ * x1i + bQ * x0r - Bi * x0i;
                xi[r1] = Ar * x1i - aQ * x1r + bQ * x0i + Bi * x0r;
            }
        }
    } else if constexpr (MR == 0) {
        // lane-crossing, same register
        #pragma unroll
        for (int r = 0; r < 32; ++r) {
            const float pr = __shfl_xor_sync(FULLMASK, xr[r], ML);
            const float pi = __shfl_xor_sync(FULLMASK, xi[r], ML);
            const bool p0 = (__popc(r & RR) & 1);
            const float aP = p0 ? Ai1 : Ai0, bP = p0 ? Br1 : Br0;
            const float nr = Ar * xr[r] + aP * xi[r] + bP * pr - Bi * pi;
            const float ni = Ar * xi[r] - aP * xr[r] + bP * pi + Bi * pr;
            xr[r] = nr;
            xi[r] = ni;
        }
    } else {
        // mixed: partner is other register AND other lane
        #pragma unroll
        for (int r = 0; r < 32; ++r) {
            const int r1 = r ^ MR;
            if (r < r1) {
                const float p0r = __shfl_xor_sync(FULLMASK, xr[r1], ML);
                const float p0i = __shfl_xor_sync(FULLMASK, xi[r1], ML);
                const float p1r = __shfl_xor_sync(FULLMASK, xr[r],  ML);
                const float p1i = __shfl_xor_sync(FULLMASK, xi[r],  ML);
                const bool q0 = (__popc(r  & RR) & 1);
                const bool q1 = (__popc(r1 & RR) & 1);
                const float aP = q0 ? Ai1 : Ai0, bP = q0 ? Br1 : Br0;
                const float aQ = q1 ? Ai1 : Ai0, bQ = q1 ? Br1 : Br0;
                const float x0r = xr[r],  x0i = xi[r];
                const float x1r = xr[r1], x1i = xi[r1];
                xr[r]  = Ar * x0r + aP * x0i + bP * p0r - Bi * p0i;
                xi[r]  = Ar * x0i - aP * x0r + bP * p0i + Bi * p0r;
                xr[r1] = Ar * x1r + aQ * x1i + bQ * p1r - Bi * p1i;
                xi[r1] = Ar * x1i - aQ * x1r + bQ * p1i + Bi * p1r;
            }
        }
    }
}

__global__ void __launch_bounds__(32)
cqv_kernel(const float* __restrict__ x,          // (2048, 49)
           const float* __restrict__ theta,      // (30,)
           const float* __restrict__ alpha_raw,  // (49,)
           const float* __restrict__ beta_raw,   // (49,)
           const float* __restrict__ head_w,     // (1, 10)
           const float* __restrict__ head_b,     // (1,)
           const float* __restrict__ logit_scale,// scalar
           float* __restrict__ out)              // (2048,)
{
    __shared__ float cg[64];
    __shared__ float sg[64];
    __shared__ float fAr[20], fAi[20], fBr[20], fBi[20];

    const int lane = threadIdx.x;
    const int sample = blockIdx.x;

    // ---- Phase A: 60 half-angle sincos, distributed over lanes ----
    #pragma unroll
    for (int t = 0; t < 2; ++t) {
        const int g = lane + 32 * t;
        if (g < 60) {
            const int b = g / 20;
            const int k = g - 20 * b;
            float half;
            if (k < 10) {
                const int f = b * 10 + k;                 // f <= 29 < 49
                const float a = alpha_raw[f];
                const float sp = fmaxf(a, 0.f) + log1pf(expf(-fabsf(a))) + 1e-6f;
                const float bt = tanhf(beta_raw[f]);
                half = 0.5f * PI_F * (sp * x[sample * INPUT_DIM + f] + bt);
            } else {
                half = 0.5f * theta[b * 10 + (k - 10)];
            }
            float s_, c_;
            sincosf(half, &s_, &c_);
            cg[g] = c_;
            sg[g] = s_;
        }
    }
    __syncwarp();

    // ---- fused SU(2) coefficients for layers 2,3 (20 gates) ----
    // a = cx*cy - i sx*sy ; b = cx*sy - i sx*cy
    if (lane < 20) {
        const int b = 1 + lane / 10;
        const int q = lane - 10 * (b - 1);
        const float cy = cg[b * 20 + q],      sy = sg[b * 20 + q];
        const float cx = cg[b * 20 + 10 + q], sx = sg[b * 20 + 10 + q];
        fAr[lane] =  cx * cy;
        fAi[lane] = -sx * sy;
        fBr[lane] =  cx * sy;
        fBi[lane] = -sx * cy;
    }
    __syncwarp();

    // ---- Phase B: layer-1 product state (A = I), fused RX*RY from |0> ----
    // f_q(0) = (cx*cy, -sx*sy), f_q(1) = (cx*sy, -sx*cy)
    float ar[32], ai[32];
    {
        float lfr = 1.f, lfi = 0.f;
        #pragma unroll
        for (int q = 5; q < 10; ++q) {
            const float cy = cg[q],      sy = sg[q];
            const float cx = cg[10 + q], sx = sg[10 + q];
            const int bbit = (lane >> (q - 5)) & 1;
            const float fre =  cx * (bbit ? sy : cy);
            const float fim = -sx * (bbit ? cy : sy);
            const float nr = lfr * fre - lfi * fim;
            const float ni = lfr * fim + lfi * fre;
            lfr = nr; lfi = ni;
        }
        ar[0] = lfr; ai[0] = lfi;
        #pragma unroll
        for (int k = 0; k < 5; ++k) {
            const float cy = cg[k],      sy = sg[k];
            const float cx = cg[10 + k], sx = sg[10 + k];
            const float f0r = cx * cy, f0i = -sx * sy;
            const float f1r = cx * sy, f1i = -sx * cy;
            #pragma unroll
            for (int r = 0; r < 16; ++r) {
                if (r < (1 << k)) {
                    const float br_ = ar[r], bi_ = ai[r];
                    ar[r + (1 << k)] = br_ * f1r - bi_ * f1i;
                    ai[r + (1 << k)] = br_ * f1i + bi_ * f1r;
                    ar[r] = br_ * f0r - bi_ * f0i;
                    ai[r] = br_ * f0i + bi_ * f0r;
                }
            }
        }
    }
    // layer-1 CNOT chain: frame A -> L (free).

    // ---- Layer 2: A = L. m_q = e_q^e_{q+1}; role_q = bits[0..q] ----
    #define G2(IDX, M, ROLE) \
        su2_g<M, ROLE>(ar, ai, fAr[IDX], fAi[IDX], fBr[IDX], fBi[IDX], lane)
    G2(0, 0x003, 0x001);
    G2(1, 0x006, 0x003);
    G2(2, 0x00C, 0x007);
    G2(3, 0x018, 0x00F);
    G2(4, 0x030, 0x01F);
    G2(5, 0x060, 0x03F);
    G2(6, 0x0C0, 0x07F);
    G2(7, 0x180, 0x0FF);
    G2(8, 0x300, 0x1FF);
    G2(9, 0x200, 0x3FF);
    // layer-2 CNOT chain: A -> L^2 (free).

    // ---- Layer 3: A = L^2. m_q = e_q^e_{q+2}; role_q = {q,q-2,...} ----
    G2(10, 0x005, 0x001);
    G2(11, 0x00A, 0x002);
    G2(12, 0x014, 0x005);
    G2(13, 0x028, 0x00A);
    G2(14, 0x050, 0x015);
    G2(15, 0x0A0, 0x02A);
    G2(16, 0x140, 0x055);
    G2(17, 0x280, 0x0AA);
    G2(18, 0x100, 0x155);
    G2(19, 0x200, 0x2AA);
    #undef G2
    // layer-3 CNOT chain: A -> L^3 (free).

    // ---- Readout: bit_q(logical) = parity(row_q(L^3) & i) ----
    const int RREG[10] = {0x01, 0x03, 0x06, 0x0C, 0x19, 0x13, 0x06, 0x0C, 0x19, 0x13};
    const int RLAN[10] = {0x00, 0x00, 0x00, 0x00, 0x00, 0x01, 0x03, 0x06, 0x0C, 0x19};

    float wl[10];
    #pragma unroll
    for (int q = 0; q < 10; ++q) {
        const float w = head_w[q];
        wl[q] = (__popc(lane & RLAN[q]) & 1) ? -w : w;
    }
    // collapse to 6 distinct register masks
    const float u0 = wl[0];          // 0x01
    const float u1 = wl[1];          // 0x03
    const float u2 = wl[2] + wl[6];  // 0x06
    const float u3 = wl[3] + wl[7];  // 0x0C
    const float u4 = wl[4] + wl[8];  // 0x19
    const float u5 = wl[5] + wl[9];  // 0x13

    float acc = 0.f;
    #pragma unroll
    for (int r = 0; r < 32; ++r) {
        const float p = ar[r] * ar[r] + ai[r] * ai[r];
        float coef = (__popc(r & 0x01) & 1) ? -u0 : u0;
        coef += (__popc(r & 0x03) & 1) ? -u1 : u1;
        coef += (__popc(r & 0x06) & 1) ? -u2 : u2;
        coef += (__popc(r & 0x0C) & 1) ? -u3 : u3;
        coef += (__popc(r & 0x19) & 1) ? -u4 : u4;
        coef += (__popc(r & 0x13) & 1) ? -u5 : u5;
        acc = fmaf(p, coef, acc);
    }
    #pragma unroll
    for (int off = 16; off > 0; off >>= 1)
        acc += __shfl_xor_sync(FULLMASK, acc, off);

    if (lane == 0) {
        const float raw = acc + head_b[0];
        const float scale = fminf(fmaxf(logit_scale[0], 0.5f), 80.0f);
        float v = scale * raw;
        v = fminf(fmaxf(v, -30.0f), 30.0f);
        out[sample] = v;
    }
}

extern "C" void kernel_launch(void* const* d_in, const int* in_sizes, int n_in,
                              void* d_out, int out_size) {
    (void)in_sizes; (void)n_in; (void)out_size;
    const float* x           = (const float*)d_in[0];
    const float* theta       = (const float*)d_in[1];
    const float* alpha_raw   = (const float*)d_in[2];
    const float* beta_raw    = (const float*)d_in[3];
    const float* head_w      = (const float*)d_in[4];
    const float* head_b      = (const float*)d_in[5];
    const float* logit_scale = (const float*)d_in[6];
    float* out = (float*)d_out;

    cqv_kernel<<<BATCH, 32>>>(x, theta, alpha_raw, beta_raw,
                              head_w, head_b, logit_scale, out);
}

// round 9
// speedup vs baseline: 1.7232x; 1.3672x over previous
#include <cuda_runtime.h>
#include <math.h>

// ---------------------------------------------------------------------------
// BinaryCQV end-to-end: 2-warp-per-sample statevector sim (64 thr/sample).
// 10 qubits: old-bit0 = warp, old-bits1-4 = register (16 amps/lane),
// old-bits5-9 = lane. CNOT-free GF(2) frame tracking + fused SU(2) gates.
// Only 2 gates (masks 0x003, 0x005) cross the warp boundary -> smem exchange.
// ---------------------------------------------------------------------------

#define FULLMASK 0xffffffffu
#define PI_F 3.14159265358979323846f
#define BATCH 2048
#define INPUT_DIM 49

// Fused SU(2) gate U=[[a,-b*],[b,a*]] with parity-dependent conjugation.
// M, ROLE are 10-bit masks in OLD physical numbering (bit0=warp, 1-4=reg, 5-9=lane).
template<int M, int ROLE>
__device__ __forceinline__ void su2_g(float (&xr)[16], float (&xi)[16],
                                      float Ar, float Ai, float Br, float Bi,
                                      int lane, int w) {
    static_assert((M & 1) == 0, "cross-warp gates handled separately");
    constexpr int MR = (M >> 1) & 15;
    constexpr int ML = (M >> 5) & 31;
    constexpr int RW = ROLE & 1;
    constexpr int RR = (ROLE >> 1) & 15;
    constexpr int RL = (ROLE >> 5) & 31;

    int lp = 0;
    if constexpr (RL != 0) lp = __popc(lane & RL) & 1;
    if constexpr (RW != 0) lp ^= w;
    const float Ai0 = lp ? Ai : -Ai;
    const float Br0 = lp ? Br : -Br;
    const float Ai1 = -Ai0, Br1 = -Br0;

    if constexpr (ML == 0) {
        // register-local pairs
        #pragma unroll
        for (int r = 0; r < 16; ++r) {
            const int r1 = r ^ MR;
            if (r < r1) {
                const bool p0 = (__popc(r & RR) & 1);
                const float aP = p0 ? Ai1 : Ai0, bP = p0 ? Br1 : Br0;
                const float aQ = p0 ? Ai0 : Ai1, bQ = p0 ? Br0 : Br1;
                const float x0r = xr[r],  x0i = xi[r];
                const float x1r = xr[r1], x1i = xi[r1];
                xr[r]  = Ar * x0r + aP * x0i + bP * x1r - Bi * x1i;
                xi[r]  = Ar * x0i - aP * x0r + bP * x1i + Bi * x1r;
                xr[r1] = Ar * x1r + aQ * x1i + bQ * x0r - Bi * x0i;
                xi[r1] = Ar * x1i - aQ * x1r + bQ * x0i + Bi * x0r;
            }
        }
    } else if constexpr (MR == 0) {
        // lane-crossing, same register
        #pragma unroll
        for (int r = 0; r < 16; ++r) {
            const float pr = __shfl_xor_sync(FULLMASK, xr[r], ML);
            const float pi = __shfl_xor_sync(FULLMASK, xi[r], ML);
            const bool p0 = (__popc(r & RR) & 1);
            const float aP = p0 ? Ai1 : Ai0, bP = p0 ? Br1 : Br0;
            const float nr = Ar * xr[r] + aP * xi[r] + bP * pr - Bi * pi;
            const float ni = Ar * xi[r] - aP * xr[r] + bP * pi + Bi * pr;
            xr[r] = nr;
            xi[r] = ni;
        }
    } else {
        // mixed: partner is other register AND other lane
        #pragma unroll
        for (int r = 0; r < 16; ++r) {
            const int r1 = r ^ MR;
            if (r < r1) {
                const float p0r = __shfl_xor_sync(FULLMASK, xr[r1], ML);
                const float p0i = __shfl_xor_sync(FULLMASK, xi[r1], ML);
                const float p1r = __shfl_xor_sync(FULLMASK, xr[r],  ML);
                const float p1i = __shfl_xor_sync(FULLMASK, xi[r],  ML);
                const bool q0 = (__popc(r  & RR) & 1);
                const bool q1 = (__popc(r1 & RR) & 1);
                const float aP = q0 ? Ai1 : Ai0, bP = q0 ? Br1 : Br0;
                const float aQ = q1 ? Ai1 : Ai0, bQ = q1 ? Br1 : Br0;
                const float x0r = xr[r],  x0i = xi[r];
                const float x1r = xr[r1], x1i = xi[r1];
                xr[r]  = Ar * x0r + aP * x0i + bP * p0r - Bi * p0i;
                xi[r]  = Ar * x0i - aP * x0r + bP * p0i + Bi * p0r;
                xr[r1] = Ar * x1r + aQ * x1i + bQ * p1r - Bi * p1i;
                xi[r1] = Ar * x1i - aQ * x1r + bQ * p1i + Bi * p1r;
            }
        }
    }
}

// Cross-warp gate: M = warp bit + reg bit MRk, ROLE = warp bit (sign warp-uniform).
template<int MRk>
__device__ __forceinline__ void cross_g(float (&xr)[16], float (&xi)[16],
                                        float Ar, float Ai, float Br, float Bi,
                                        int lane, int w,
                                        float (&exR)[2][16][32],
                                        float (&exI)[2][16][32]) {
    __syncthreads();   // previous smem use complete
    #pragma unroll
    for (int r = 0; r < 16; ++r) {
        exR[w][r][lane] = xr[r];
        exI[w][r][lane] = xi[r];
    }
    __syncthreads();
    const float AiE = w ? Ai : -Ai;   // lp = w (ROLE = warp bit)
    const float BrE = w ? Br : -Br;
    #pragma unroll
    for (int r = 0; r < 16; ++r) {
        const float pr = exR[w ^ 1][r ^ MRk][lane];
        const float pi = exI[w ^ 1][r ^ MRk][lane];
        const float nr = Ar * xr[r] + AiE * xi[r] + BrE * pr - Bi * pi;
        const float ni = Ar * xi[r] - AiE * xr[r] + BrE * pi + Bi * pr;
        xr[r] = nr;
        xi[r] = ni;
    }
}

__global__ void __launch_bounds__(64)
cqv_kernel(const float* __restrict__ x,          // (2048, 49)
           const float* __restrict__ theta,      // (30,)
           const float* __restrict__ alpha_raw,  // (49,)
           const float* __restrict__ beta_raw,   // (49,)
           const float* __restrict__ head_w,     // (1, 10)
           const float* __restrict__ head_b,     // (1,)
           const float* __restrict__ logit_scale,// scalar
           float* __restrict__ out)              // (2048,)
{
    __shared__ float cg[64];
    __shared__ float sg[64];
    __shared__ float fAr[20], fAi[20], fBr[20], fBi[20];
    __shared__ float exR[2][16][32];
    __shared__ float exI[2][16][32];
    __shared__ float partial[2];

    const int t = threadIdx.x;
    const int w = t >> 5;
    const int lane = t & 31;
    const int sample = blockIdx.x;

    // ---- Phase A: 60 half-angle sincos (one per thread) ----
    if (t < 60) {
        const int b = t / 20;
        const int k = t - 20 * b;
        float half;
        if (k < 10) {
            const int f = b * 10 + k;                 // f <= 29 < 49
            const float a = alpha_raw[f];
            const float sp = fmaxf(a, 0.f) + log1pf(expf(-fabsf(a))) + 1e-6f;
            const float bt = tanhf(beta_raw[f]);
            half = 0.5f * PI_F * (sp * x[sample * INPUT_DIM + f] + bt);
        } else {
            half = 0.5f * theta[b * 10 + (k - 10)];
        }
        float s_, c_;
        sincosf(half, &s_, &c_);
        cg[t] = c_;
        sg[t] = s_;
    }
    __syncthreads();

    // ---- fused SU(2) coefficients for layers 2,3 (20 gates) ----
    if (t < 20) {
        const int b = 1 + t / 10;
        const int q = t - 10 * (b - 1);
        const float cy = cg[b * 20 + q],      sy = sg[b * 20 + q];
        const float cx = cg[b * 20 + 10 + q], sx = sg[b * 20 + 10 + q];
        fAr[t] =  cx * cy;
        fAi[t] = -sx * sy;
        fBr[t] =  cx * sy;
        fBi[t] = -sx * cy;
    }
    __syncthreads();

    // ---- Layer 1: product state (A = I), fused RX*RY from |0> ----
    // f_q(0) = (cx*cy, -sx*sy), f_q(1) = (cx*sy, -sx*cy)
    float xr[16], xi[16];
    {
        // per-thread scalar factor: qubit 0 (warp bit) and qubits 5-9 (lane bits)
        float lfr, lfi;
        {
            const float cy = cg[0], sy = sg[0];
            const float cx = cg[10], sx = sg[10];
            lfr =  cx * (w ? sy : cy);
            lfi = -sx * (w ? cy : sy);
        }
        #pragma unroll
        for (int q = 5; q < 10; ++q) {
            const float cy = cg[q],      sy = sg[q];
            const float cx = cg[10 + q], sx = sg[10 + q];
            const int bbit = (lane >> (q - 5)) & 1;
            const float fre =  cx * (bbit ? sy : cy);
            const float fim = -sx * (bbit ? cy : sy);
            const float nr = lfr * fre - lfi * fim;
            const float ni = lfr * fim + lfi * fre;
            lfr = nr; lfi = ni;
        }
        xr[0] = lfr; xi[0] = lfi;
        // doubling over qubits 1..4 (reg bits 0..3)
        #pragma unroll
        for (int k = 0; k < 4; ++k) {
            const float cy = cg[1 + k],  sy = sg[1 + k];
            const float cx = cg[11 + k], sx = sg[11 + k];
            const float f0r = cx * cy, f0i = -sx * sy;
            const float f1r = cx * sy, f1i = -sx * cy;
            #pragma unroll
            for (int r = 0; r < 8; ++r) {
                if (r < (1 << k)) {
                    const float br_ = xr[r], bi_ = xi[r];
                    xr[r + (1 << k)] = br_ * f1r - bi_ * f1i;
                    xi[r + (1 << k)] = br_ * f1i + bi_ * f1r;
                    xr[r] = br_ * f0r - bi_ * f0i;
                    xi[r] = br_ * f0i + bi_ * f0r;
                }
            }
        }
    }
    // layer-1 CNOT chain: frame A -> L (free).

    // ---- Layer 2: A = L. m_q = e_q^e_{q+1}; role_q = bits[0..q] ----
    #define G2(IDX, M, ROLE) \
        su2_g<M, ROLE>(xr, xi, fAr[IDX], fAi[IDX], fBr[IDX], fBi[IDX], lane, w)
    cross_g<0x01>(xr, xi, fAr[0], fAi[0], fBr[0], fBi[0], lane, w, exR, exI);
    G2(1, 0x006, 0x003);
    G2(2, 0x00C, 0x007);
    G2(3, 0x018, 0x00F);
    G2(4, 0x030, 0x01F);
    G2(5, 0x060, 0x03F);
    G2(6, 0x0C0, 0x07F);
    G2(7, 0x180, 0x0FF);
    G2(8, 0x300, 0x1FF);
    G2(9, 0x200, 0x3FF);
    // layer-2 CNOT chain: A -> L^2 (free).

    // ---- Layer 3: A = L^2. m_q = e_q^e_{q+2}; role_q = {q,q-2,...} ----
    cross_g<0x02>(xr, xi, fAr[10], fAi[10], fBr[10], fBi[10], lane, w, exR, exI);
    G2(11, 0x00A, 0x002);
    G2(12, 0x014, 0x005);
    G2(13, 0x028, 0x00A);
    G2(14, 0x050, 0x015);
    G2(15, 0x0A0, 0x02A);
    G2(16, 0x140, 0x055);
    G2(17, 0x280, 0x0AA);
    G2(18, 0x100, 0x155);
    G2(19, 0x200, 0x2AA);
    #undef G2
    // layer-3 CNOT chain: A -> L^3 (free).

    // ---- Readout: bit_q = parity(row_q(L^3) & i); rows decomposed w/reg/lane ----
    // q:      0     1     2     3     4     5     6     7     8     9
    // RW:     1     1     0     0     1     1     0     0     1     1
    // RR:   0x0   0x1   0x3   0x6   0xC   0x9   0x3   0x6   0xC   0x9
    // RL:     0     0     0     0     0  0x01  0x03  0x06  0x0C  0x19
    const int RWq[10] = {1, 1, 0, 0, 1, 1, 0, 0, 1, 1};
    const int RLq[10] = {0, 0, 0, 0, 0, 0x01, 0x03, 0x06, 0x0C, 0x19};

    float wl[10];
    #pragma unroll
    for (int q = 0; q < 10; ++q) {
        const float hw = head_w[q];
        const int sgn = (__popc(lane & RLq[q]) ^ (RWq[q] & w)) & 1;
        wl[q] = sgn ? -hw : hw;
    }
    const float u0 = wl[0];          // reg mask 0x0 (constant)
    const float u1 = wl[1];          // 0x1
    const float u2 = wl[2] + wl[6];  // 0x3
    const float u3 = wl[3] + wl[7];  // 0x6
    const float u4 = wl[4] + wl[8];  // 0xC
    const float u5 = wl[5] + wl[9];  // 0x9

    float acc = 0.f;
    #pragma unroll
    for (int r = 0; r < 16; ++r) {
        const float p = xr[r] * xr[r] + xi[r] * xi[r];
        float coef = u0;
        coef += (__popc(r & 0x1) & 1) ? -u1 : u1;
        coef += (__popc(r & 0x3) & 1) ? -u2 : u2;
        coef += (__popc(r & 0x6) & 1) ? -u3 : u3;
        coef += (__popc(r & 0xC) & 1) ? -u4 : u4;
        coef += (__popc(r & 0x9) & 1) ? -u5 : u5;
        acc = fmaf(p, coef, acc);
    }
    #pragma unroll
    for (int off = 16; off > 0; off >>= 1)
        acc += __shfl_xor_sync(FULLMASK, acc, off);

    if (lane == 0) partial[w] = acc;
    __syncthreads();

    if (t == 0) {
        const float raw = partial[0] + partial[1] + head_b[0];
        const float scale = fminf(fmaxf(logit_scale[0], 0.5f), 80.0f);
        float v = scale * raw;
        v = fminf(fmaxf(v, -30.0f), 30.0f);
        out[sample] = v;
    }
}

extern "C" void kernel_launch(void* const* d_in, const int* in_sizes, int n_in,
                              void* d_out, int out_size) {
    (void)in_sizes; (void)n_in; (void)out_size;
    const float* x           = (const float*)d_in[0];
    const float* theta       = (const float*)d_in[1];
    const float* alpha_raw   = (const float*)d_in[2];
    const float* beta_raw    = (const float*)d_in[3];
    const float* head_w      = (const float*)d_in[4];
    const float* head_b      = (const float*)d_in[5];
    const float* logit_scale = (const float*)d_in[6];
    float* out = (float*)d_out;

    cqv_kernel<<<BATCH, 64>>>(x, theta, alpha_raw, beta_raw,
                              head_w, head_b, logit_scale, out);
}